// round 12
// baseline (speedup 1.0000x reference)
#include <cuda_runtime.h>
#include <math.h>

// Problem constants
#define BB   64
#define TT   512
#define EE   300
#define HDIM 256
#define G4   1024
#define KTAG 20
#define GRID_P 128

typedef unsigned long long ull;

// ---------------- scratch ----------------
// g_X blocked: [dir][bt][ks][t][b_l][gate][k_l]
__device__ float g_X[(size_t)2 * BB * TT * G4];
// g_h blocked: [dir][bt][t][b_l][k]
__device__ float g_h[(size_t)2 * BB * TT * HDIM];
__device__ float g_emis[(size_t)BB * TT * KTAG];
// per-(group, producerCTA, producerWarp[4]) monotone flags, 128B apart
__device__ int   g_flagsB[16 * 8 * 4 * 32];

// ---------------- packed fp32x2 helpers ----------------
__device__ __forceinline__ ull ffma2(ull a, ull b, ull c) {
    ull d;
    asm("fma.rn.f32x2 %0, %1, %2, %3;" : "=l"(d) : "l"(a), "l"(b), "l"(c));
    return d;
}
__device__ __forceinline__ ull f2u2(float x, float y) {
    ull v;
    asm("mov.b64 %0, {%1, %2};" : "=l"(v) : "f"(x), "f"(y));
    return v;
}
__device__ __forceinline__ float2 u2f2(ull v) {
    float2 f;
    asm("mov.b64 {%0, %1}, %2;" : "=f"(f.x), "=f"(f.y) : "l"(v));
    return f;
}

#define BARL() asm volatile("bar.sync 4, 128;" ::: "memory")
#define BARG() asm volatile("bar.sync 5, 256;" ::: "memory")

__device__ __forceinline__ float sigf(float x) { return 1.f / (1.f + expf(-x)); }

// =====================================================================
// FUSED persistent kernel: 128 CTAs x 384 threads.
//   warps 0-7  (tid 0..255)   : gates GEMM (2 per SMSP -> dense fill)
//   warps 8-11 (tid 256..383) : LSTM (1 per SMSP, HIGH wid priority)
// LSTM warp w covers kk-window [64w, 64w+64); final pass: thread owns
// 2 (b,k) pairs. Per-(CTA,warp) release flags; consumer warp w polls
// producer CTAs 2w,2w+1 (their 4 warp-flags each). One bar/step.
// =====================================================================
#define WP_ULL (4 * 128 * 33)
// Wp 135168 | hsm 8192 | ps 2x16384 | As 4608 | Bs 4352 | tok 256 | xprog 128
#define SMEM_FUSED 185472

__global__ void __launch_bounds__(384, 1)
fused_persistent_kernel(const int* __restrict__ sentence,
                        const int* __restrict__ lengths,
                        const float* __restrict__ emb,
                        const float* __restrict__ Wf_ih,
                        const float* __restrict__ bf,
                        const float* __restrict__ Wb_ih,
                        const float* __restrict__ bb,
                        const float* __restrict__ Wf_hh,
                        const float* __restrict__ Wb_hh)
{
    extern __shared__ char smraw[];
    ull*   Wp   = (ull*)smraw;                   // [4][128][33]
    float* hsm  = (float*)(Wp + WP_ULL);         // 4 warps x [8b][64k] warp-private
    float* ps   = hsm + 2048;                    // [2][4][4][8][32] double-buffered psum
    float* As   = ps + 8192;                     // [16][72]
    float* Bs   = As + 16 * 72;                  // [16][68]
    int*   tok2 = (int*)(Bs + 16 * 68);          // [64]
    int*   xprog = tok2 + 64;
    ull*   hsmu = (ull*)hsm;

    const int bx  = blockIdx.x;
    const int dir = bx & 1;
    const int ks  = (bx >> 1) & 7;
    const int bt  = bx >> 4;
    const int k0s = ks * 32;
    const int b0  = bt * 8;
    const int tid = threadIdx.x;
    const int grp = bt * 2 + dir;

    const float* __restrict__ Whh  = dir ? Wb_hh : Wf_hh;
    const float* __restrict__ Wih  = dir ? Wb_ih : Wf_ih;
    const float* __restrict__ bias = dir ? bb    : bf;

    // one-time init (all 384 threads)
    for (int i = tid; i < 128 * 128; i += 384) {
        int r = i >> 7;
        int j = i & 127;
        int g = r >> 5, kl = r & 31;
        ull v = *(const ull*)(Whh + (size_t)(g * 256 + k0s + kl) * HDIM + 2 * j);
        Wp[(g * 128 + j) * 33 + kl] = v;
    }
    for (int i = tid; i < 2048; i += 384) hsm[i] = 0.f;   // h(-1)=0
    if (tid == 0) *xprog = 0;
    __syncthreads();

    if (tid >= 256) {
        // ================= LSTM half (warps 8-11, HIGH priority) =========
        const int ltid = tid - 256;        // 0..127
        const int lane = ltid & 31;
        const int warp = ltid >> 5;        // 0..3
        const int bA   = warp * 2;         // final-pass batches bA, bA+1

        // my publish flag: (grp, myCTA=ks, myWarp=warp)
        int* myflag = &g_flagsB[(((grp * 8) + ks) * 4 + warp) * 32];
        // my producers: CTAs 2w, 2w+1 (k window 64w..64w+64), 4 warps each
        int* prodflags = lane < 8
            ? &g_flagsB[(((grp * 8) + (warp * 2 + (lane >> 2))) * 4 + (lane & 3)) * 32]
            : &g_flagsB[(((grp * 8) + warp * 2) * 4) * 32];

        const int base = *(volatile int*)myflag;

        const size_t ctaX = ((size_t)((dir * 8 + bt) * 8 + ks)) * (TT * 1024);
        const float* xmeA = g_X + ctaX + bA * 128 + lane;         // batch bA
        const float* xmeB = g_X + ctaX + (bA + 1) * 128 + lane;   // batch bA+1
        const size_t grpH = ((size_t)(dir * 8 + bt)) * (TT * 8 * HDIM);
        float* hmeA = g_h + grpH + bA * HDIM + (k0s + lane);
        float* hmeB = g_h + grpH + (bA + 1) * HDIM + (k0s + lane);
        // reload source: h(t-1), my warp's k-window [64w, +64), b=lane>>2, 16 floats
        const float* hsrc = g_h + grpH + (lane >> 2) * HDIM + warp * 64 + (lane & 3) * 16;
        float* hdst = hsm + warp * 512 + (lane >> 2) * 64 + (lane & 3) * 16;

        float cA = 0.f, cB = 0.f;

        for (int t = 0; t < TT; t++) {
            if (t > 0) {
                const int target = base + t;
                int fv = 0;
                bool done;
                do {
                    if (lane < 8)
                        asm volatile("ld.acquire.gpu.global.b32 %0, [%1];"
                                     : "=r"(fv) : "l"(prodflags) : "memory");
                    done = __all_sync(0xffffffffu, (lane >= 8) || (fv >= target));
                } while (!done);
                __syncwarp();

                const float* src = hsrc + (size_t)(t - 1) * (8 * HDIM);
                float4 v0 = *(const float4*)src;
                float4 v1 = *(const float4*)(src + 4);
                float4 v2 = *(const float4*)(src + 8);
                float4 v3 = *(const float4*)(src + 12);
                *(float4*)hdst        = v0;
                *(float4*)(hdst + 4)  = v1;
                *(float4*)(hdst + 8)  = v2;
                *(float4*)(hdst + 12) = v3;
                __syncwarp();
            }

            // wait for GEMM warps to have produced X(t)
            int xv;
            do {
                asm volatile("ld.acquire.cta.b32 %0, [%1];" : "=r"(xv) : "l"(xprog) : "memory");
            } while (xv < t + 1);

            const float* xrA = xmeA + (size_t)t * 1024;
            const float* xrB = xmeB + (size_t)t * 1024;
            float xiA = xrA[0], xfA = xrA[32], xgA = xrA[64], xoA = xrA[96];
            float xiB = xrB[0], xfB = xrB[32], xgB = xrB[64], xoB = xrB[96];

            // ---- partial dot products over my warp's 64-wide kk window ----
            ull acc[4][8];
#pragma unroll
            for (int g = 0; g < 4; g++)
#pragma unroll
                for (int b = 0; b < 8; b++) acc[g][b] = 0ull;

            const ull* hW = hsmu + warp * 256;   // [8b][32 kk-pairs]
            const int kkb = warp * 32;
#pragma unroll 4
            for (int c = 0; c < 32; c++) {
                int kk2 = kkb + c;
                ull w0 = Wp[(0 * 128 + kk2) * 33 + lane];
                ull w1 = Wp[(1 * 128 + kk2) * 33 + lane];
                ull w2 = Wp[(2 * 128 + kk2) * 33 + lane];
                ull w3 = Wp[(3 * 128 + kk2) * 33 + lane];
#pragma unroll
                for (int b = 0; b < 8; b++) {
                    ull h2 = hW[b * 32 + c];     // warp-uniform broadcast
                    acc[0][b] = ffma2(h2, w0, acc[0][b]);
                    acc[1][b] = ffma2(h2, w1, acc[1][b]);
                    acc[2][b] = ffma2(h2, w2, acc[2][b]);
                    acc[3][b] = ffma2(h2, w3, acc[3][b]);
                }
            }

            float* pb = ps + (t & 1) * 4096;
#pragma unroll
            for (int g = 0; g < 4; g++)
#pragma unroll
                for (int b = 0; b < 8; b++) {
                    float2 s = u2f2(acc[g][b]);
                    pb[((warp * 4 + g) * 8 + b) * 32 + lane] = s.x + s.y;
                }
            BARL();   // the ONLY per-step LSTM barrier

            // reduce 4 producer warps for (bA,k) and (bA+1,k), k=k0s+lane
            float sA0 = 0.f, sA1 = 0.f, sA2 = 0.f, sA3 = 0.f;
            float sB0 = 0.f, sB1 = 0.f, sB2 = 0.f, sB3 = 0.f;
#pragma unroll
            for (int w = 0; w < 4; w++) {
                sA0 += pb[((w * 4 + 0) * 8 + bA) * 32 + lane];
                sA1 += pb[((w * 4 + 1) * 8 + bA) * 32 + lane];
                sA2 += pb[((w * 4 + 2) * 8 + bA) * 32 + lane];
                sA3 += pb[((w * 4 + 3) * 8 + bA) * 32 + lane];
                sB0 += pb[((w * 4 + 0) * 8 + bA + 1) * 32 + lane];
                sB1 += pb[((w * 4 + 1) * 8 + bA + 1) * 32 + lane];
                sB2 += pb[((w * 4 + 2) * 8 + bA + 1) * 32 + lane];
                sB3 += pb[((w * 4 + 3) * 8 + bA + 1) * 32 + lane];
            }
            float giA = xiA + sA0, gfA = xfA + sA1, ggA = xgA + sA2, goA = xoA + sA3;
            float giB = xiB + sB0, gfB = xfB + sB1, ggB = xgB + sB2, goB = xoB + sB3;

            cA = sigf(gfA) * cA + sigf(giA) * tanhf(ggA);
            float hA = sigf(goA) * tanhf(cA);
            cB = sigf(gfB) * cB + sigf(giB) * tanhf(ggB);
            float hB = sigf(goB) * tanhf(cB);
            hmeA[(size_t)t * (8 * HDIM)] = hA;
            hmeB[(size_t)t * (8 * HDIM)] = hB;

            if (t + 1 < TT) {
                __syncwarp();
                if (lane == 0)
                    asm volatile("st.release.gpu.global.b32 [%0], %1;"
                                 :: "l"(myflag), "r"(base + t + 1) : "memory");
            }
        }
    } else {
        // ================= GEMM half (warps 0-7, LOW priority) ===========
        const int tid2 = tid;              // 0..255
        const int tx = tid2 & 15;          // n quad
        const int ty = tid2 >> 4;          // m quad (0..15)
        const int lrow = tid2 >> 2;        // load row 0..63
        const int kc4  = (tid2 & 3) * 4;   // k sub-chunk
        const size_t xbase = ((size_t)((dir * 8 + bt) * 8 + ks)) * (TT * 1024);

        for (int mt = 0; mt < 64; mt++) {
            if (tid2 < 64) {
                int tloc = tid2 >> 3, b_l = tid2 & 7;
                int t = mt * 8 + tloc, b = b0 + b_l;
                int tt = t;
                if (dir) { int len = lengths[b]; tt = (t < len) ? (len - 1 - t) : t; }
                tok2[tid2] = sentence[b * TT + tt];
            }
            BARG();

            const float* erow = emb + (size_t)tok2[lrow] * EE;

            for (int nt = 0; nt < 2; nt++) {
                ull acc[2][4];
#pragma unroll
                for (int i = 0; i < 2; i++)
#pragma unroll
                    for (int j = 0; j < 4; j++) acc[i][j] = 0ull;

                const int nglob = nt * 64 + lrow;
                const float* wrow = Wih + (size_t)((nglob >> 5) * 256 + k0s + (nglob & 31)) * EE;

                for (int k0 = 0; k0 < 304; k0 += 16) {
                    const int kb = k0 + kc4;
                    // A tile [k][m]: 4 floats per thread
                    if (kb + 4 <= EE) {
                        float4 v = *(const float4*)(erow + kb);
                        As[(kc4 + 0) * 72 + lrow] = v.x;
                        As[(kc4 + 1) * 72 + lrow] = v.y;
                        As[(kc4 + 2) * 72 + lrow] = v.z;
                        As[(kc4 + 3) * 72 + lrow] = v.w;
                    } else {
#pragma unroll
                        for (int i = 0; i < 4; i++)
                            As[(kc4 + i) * 72 + lrow] = (kb + i < EE) ? erow[kb + i] : 0.f;
                    }
                    // B tile [k][n]
                    if (kb + 4 <= EE) {
                        float4 v = *(const float4*)(wrow + kb);
                        Bs[(kc4 + 0) * 68 + lrow] = v.x;
                        Bs[(kc4 + 1) * 68 + lrow] = v.y;
                        Bs[(kc4 + 2) * 68 + lrow] = v.z;
                        Bs[(kc4 + 3) * 68 + lrow] = v.w;
                    } else {
#pragma unroll
                        for (int i = 0; i < 4; i++)
                            Bs[(kc4 + i) * 68 + lrow] = (kb + i < EE) ? wrow[kb + i] : 0.f;
                    }
                    BARG();

#pragma unroll
                    for (int kk = 0; kk < 16; kk++) {
                        ulonglong2 a0 = *(const ulonglong2*)&As[kk * 72 + ty * 4];
                        float4 bv = *(const float4*)&Bs[kk * 68 + tx * 4];
                        ull q0 = f2u2(bv.x, bv.x);
                        ull q1 = f2u2(bv.y, bv.y);
                        ull q2 = f2u2(bv.z, bv.z);
                        ull q3 = f2u2(bv.w, bv.w);
                        acc[0][0] = ffma2(a0.x, q0, acc[0][0]);
                        acc[0][1] = ffma2(a0.x, q1, acc[0][1]);
                        acc[0][2] = ffma2(a0.x, q2, acc[0][2]);
                        acc[0][3] = ffma2(a0.x, q3, acc[0][3]);
                        acc[1][0] = ffma2(a0.y, q0, acc[1][0]);
                        acc[1][1] = ffma2(a0.y, q1, acc[1][1]);
                        acc[1][2] = ffma2(a0.y, q2, acc[1][2]);
                        acc[1][3] = ffma2(a0.y, q3, acc[1][3]);
                    }
                    BARG();
                }

                const int ng = nt * 64 + tx * 4;
                const float* bp2 = bias + (ng >> 5) * 256 + k0s + (ng & 31);
                float4 bv4;
                bv4.x = bp2[0]; bv4.y = bp2[1]; bv4.z = bp2[2]; bv4.w = bp2[3];
#pragma unroll
                for (int mp = 0; mp < 2; mp++) {
                    float2 c0 = u2f2(acc[mp][0]);
                    float2 c1 = u2f2(acc[mp][1]);
                    float2 c2 = u2f2(acc[mp][2]);
                    float2 c3 = u2f2(acc[mp][3]);
#pragma unroll
                    for (int h = 0; h < 2; h++) {
                        int m = ty * 4 + 2 * mp + h;
                        int tloc = m >> 3, b_l = m & 7;
                        size_t off = xbase + (size_t)(mt * 8 + tloc) * 1024 + b_l * 128 + ng;
                        float4 v;
                        if (h == 0) { v.x = c0.x + bv4.x; v.y = c1.x + bv4.y; v.z = c2.x + bv4.z; v.w = c3.x + bv4.w; }
                        else        { v.x = c0.y + bv4.x; v.y = c1.y + bv4.y; v.z = c2.y + bv4.z; v.w = c3.y + bv4.w; }
                        *(float4*)&g_X[off] = v;
                    }
                }
            }
            BARG();
            if (tid2 == 0) {
                int val = (mt + 1) * 8;
                asm volatile("st.release.cta.b32 [%0], %1;" :: "l"(xprog), "r"(val) : "memory");
            }
        }
    }
}

// =====================================================================
// Kernel 3: emissions (unchanged)
// =====================================================================
__global__ void emis_kernel(const int* __restrict__ lengths,
                            const float* __restrict__ W_out,
                            const float* __restrict__ b_out)
{
    __shared__ float Wsm[KTAG * 2 * HDIM];
    __shared__ float bsm[KTAG];

    const int tid = threadIdx.x;
    for (int i = tid; i < KTAG * 2 * HDIM; i += 256) Wsm[i] = W_out[i];
    if (tid < KTAG) bsm[tid] = b_out[tid];
    __syncthreads();

    const int warp = tid >> 5;
    const int lane = tid & 31;
    const int r = blockIdx.x * 8 + warp;
    const int b = r >> 9;
    const int t = r & 511;
    const int len = lengths[b];
    const int tr  = (t < len) ? (len - 1 - t) : t;
    const int bt = b >> 3, b_l = b & 7;

    const float* hf = g_h + ((size_t)(0 * 8 + bt)) * (TT * 8 * HDIM)
                          + (size_t)t  * (8 * HDIM) + b_l * HDIM;
    const float* hb = g_h + ((size_t)(1 * 8 + bt)) * (TT * 8 * HDIM)
                          + (size_t)tr * (8 * HDIM) + b_l * HDIM;

    float x[16];
#pragma unroll
    for (int i = 0; i < 8; i++) x[i]     = hf[lane + 32 * i];
#pragma unroll
    for (int i = 0; i < 8; i++) x[8 + i] = hb[lane + 32 * i];

    for (int kk = 0; kk < KTAG; kk++) {
        const float* w = Wsm + (size_t)kk * (2 * HDIM);
        float s = 0.f;
#pragma unroll
        for (int i = 0; i < 8; i++) s += x[i]     * w[lane + 32 * i];
#pragma unroll
        for (int i = 0; i < 8; i++) s += x[8 + i] * w[HDIM + lane + 32 * i];
#pragma unroll
        for (int off = 16; off; off >>= 1) s += __shfl_xor_sync(0xffffffffu, s, off);
        if (lane == 0) g_emis[((size_t)b * TT + t) * KTAG + kk] = s + bsm[kk];
    }
}

// =====================================================================
// Kernel 4: Viterbi (unchanged)
// =====================================================================
#define VIT_SMEM 53248
#define VCOMB(av, ai_, bv, bi_) { if ((bv) > (av)) { (av) = (bv); (ai_) = (bi_); } }

__global__ void viterbi_kernel(const int* __restrict__ lengths,
                               const int* __restrict__ stop_id_p,
                               const float* __restrict__ trans,
                               float* __restrict__ out)
{
    extern __shared__ char vsm[];
    float* emis_s = (float*)vsm;
    float* trp    = emis_s + TT * KTAG;
    float* term   = trp + KTAG * 21;
    unsigned char* bp = (unsigned char*)(term + KTAG);

    const int b = blockIdx.x;
    const int lane = threadIdx.x;

    for (int i = lane; i < TT * KTAG; i += 32)
        emis_s[i] = g_emis[(size_t)b * TT * KTAG + i];
    for (int i = lane; i < KTAG * KTAG; i += 32)
        trp[(i / KTAG) * 21 + (i % KTAG)] = trans[i];
    __syncwarp();

    const int len  = lengths[b];
    const int stop = *stop_id_p;
    const float* trl = trp + (lane < KTAG ? lane : 0) * 21;

    float d = 0.f;

    for (int t = 0; t < TT; t++) {
        float em = (lane < KTAG) ? emis_s[t * KTAG + lane] : 0.f;

        float v[KTAG];
#pragma unroll
        for (int p = 0; p < KTAG; p++)
            v[p] = __shfl_sync(0xffffffffu, d, p) + trl[p];

        float w10[10]; int i10[10];
#pragma unroll
        for (int i = 0; i < 10; i++) {
            w10[i] = v[2 * i]; i10[i] = 2 * i;
            VCOMB(w10[i], i10[i], v[2 * i + 1], 2 * i + 1);
        }
        float w5[5]; int i5[5];
#pragma unroll
        for (int i = 0; i < 5; i++) {
            w5[i] = w10[2 * i]; i5[i] = i10[2 * i];
            VCOMB(w5[i], i5[i], w10[2 * i + 1], i10[2 * i + 1]);
        }
        float bv0 = w5[0]; int bi0 = i5[0];
        VCOMB(bv0, bi0, w5[1], i5[1]);
        float bv1 = w5[2]; int bi1 = i5[2];
        VCOMB(bv1, bi1, w5[3], i5[3]);
        VCOMB(bv0, bi0, bv1, bi1);
        VCOMB(bv0, bi0, w5[4], i5[4]);

        bool valid = (t < len);
        if (lane < KTAG) {
            float nd = bv0 + em;
            int bpv  = valid ? bi0 : lane;
            d = valid ? nd : d;
            bp[t * KTAG + lane] = (unsigned char)bpv;
        }
    }

    if (lane < KTAG) term[lane] = d + trp[stop * 21 + lane];
    __syncwarp();

    if (lane == 0) {
        float best = -3.4e38f; int arg = 0;
        for (int j = 0; j < KTAG; j++)
            if (term[j] > best) { best = term[j]; arg = j; }
        out[b] = best;
        float* po = out + BB + (size_t)b * (TT + 1);
        po[TT] = (float)arg;
        int tag = arg;
        for (int t = TT - 1; t >= 0; t--) {
            tag = bp[t * KTAG + tag];
            po[t] = (float)tag;
        }
    }
}

// =====================================================================
// launch
// =====================================================================
extern "C" void kernel_launch(void* const* d_in, const int* in_sizes, int n_in,
                              void* d_out, int out_size)
{
    (void)in_sizes; (void)n_in; (void)out_size;
    const int*   sentence = (const int*)d_in[0];
    const int*   lengths  = (const int*)d_in[1];
    const int*   stop_id  = (const int*)d_in[3];
    const float* emb      = (const float*)d_in[4];
    const float* Wf_ih    = (const float*)d_in[5];
    const float* Wf_hh    = (const float*)d_in[6];
    const float* bf       = (const float*)d_in[7];
    const float* Wb_ih    = (const float*)d_in[8];
    const float* Wb_hh    = (const float*)d_in[9];
    const float* bb       = (const float*)d_in[10];
    const float* W_out    = (const float*)d_in[11];
    const float* b_out    = (const float*)d_in[12];
    const float* trans    = (const float*)d_in[13];
    float* out = (float*)d_out;

    static int attr_set = 0;
    if (!attr_set) {
        cudaFuncSetAttribute(fused_persistent_kernel,
                             cudaFuncAttributeMaxDynamicSharedMemorySize, SMEM_FUSED);
        cudaFuncSetAttribute(viterbi_kernel,
                             cudaFuncAttributeMaxDynamicSharedMemorySize, VIT_SMEM);
        attr_set = 1;
    }

    fused_persistent_kernel<<<GRID_P, 384, SMEM_FUSED>>>(
        sentence, lengths, emb, Wf_ih, bf, Wb_ih, bb, Wf_hh, Wb_hh);

    emis_kernel<<<BB * TT / 8, 256>>>(lengths, W_out, b_out);

    viterbi_kernel<<<BB, 32, VIT_SMEM>>>(lengths, stop_id, trans, out);
}

// round 13
// speedup vs baseline: 1.0661x; 1.0661x over previous
#include <cuda_runtime.h>
#include <math.h>

// Problem constants
#define BB   64
#define TT   512
#define EE   300
#define HDIM 256
#define G4   1024
#define KTAG 20
#define GRID_P 128

typedef unsigned long long ull;

// ---------------- scratch ----------------
// g_X blocked: [dir][bt][ks][t][b_l][gate][k_l]
__device__ float g_X[(size_t)2 * BB * TT * G4];
// g_h blocked: [dir][bt][t][b_l][k]
__device__ float g_h[(size_t)2 * BB * TT * HDIM];
__device__ float g_emis[(size_t)BB * TT * KTAG];
// per-(group, producerCTA, producerWarp[4]) monotone flags, 128B apart
__device__ int   g_flagsB[16 * 8 * 4 * 32];

// ---------------- packed fp32x2 helpers ----------------
__device__ __forceinline__ ull ffma2(ull a, ull b, ull c) {
    ull d;
    asm("fma.rn.f32x2 %0, %1, %2, %3;" : "=l"(d) : "l"(a), "l"(b), "l"(c));
    return d;
}
__device__ __forceinline__ ull f2u2(float x, float y) {
    ull v;
    asm("mov.b64 %0, {%1, %2};" : "=l"(v) : "f"(x), "f"(y));
    return v;
}
__device__ __forceinline__ float2 u2f2(ull v) {
    float2 f;
    asm("mov.b64 {%0, %1}, %2;" : "=f"(f.x), "=f"(f.y) : "l"(v));
    return f;
}

#define BARL() asm volatile("bar.sync 4, 128;" ::: "memory")
#define BARG() asm volatile("bar.sync 5, 256;" ::: "memory")

__device__ __forceinline__ float sigf(float x) { return 1.f / (1.f + expf(-x)); }

// =====================================================================
// FUSED persistent kernel: 128 CTAs x 384 threads.
//   warps 0-7  (tid 0..255)   : gates GEMM, 8x8 microtile (low LDS/FLOP)
//   warps 8-11 (tid 256..383) : LSTM (1/SMSP, HIGH wid priority),
//                               h loaded as pairs (halved broadcast wf)
// =====================================================================
#define WP_ULL (4 * 128 * 33)
// Wp 135168 | hsm 8192 | ps 32768 | As 8448 | Bs 8448 | tok 512 | xprog 128
#define SMEM_FUSED 193664

__global__ void __launch_bounds__(384, 1)
fused_persistent_kernel(const int* __restrict__ sentence,
                        const int* __restrict__ lengths,
                        const float* __restrict__ emb,
                        const float* __restrict__ Wf_ih,
                        const float* __restrict__ bf,
                        const float* __restrict__ Wb_ih,
                        const float* __restrict__ bb,
                        const float* __restrict__ Wf_hh,
                        const float* __restrict__ Wb_hh)
{
    extern __shared__ char smraw[];
    ull*   Wp   = (ull*)smraw;                   // [4][128][33]
    float* hsm  = (float*)(Wp + WP_ULL);         // 4 warps x [8b][64k]
    float* ps   = hsm + 2048;                    // [2][4][4][8][32] psum
    float* As   = ps + 8192;                     // [16][132]
    float* Bs   = As + 16 * 132;                 // [16][132]
    int*   tok2 = (int*)(Bs + 16 * 132);         // [128]
    int*   xprog = tok2 + 128;
    ull*   hsmu = (ull*)hsm;

    const int bx  = blockIdx.x;
    const int dir = bx & 1;
    const int ks  = (bx >> 1) & 7;
    const int bt  = bx >> 4;
    const int k0s = ks * 32;
    const int b0  = bt * 8;
    const int tid = threadIdx.x;
    const int grp = bt * 2 + dir;

    const float* __restrict__ Whh  = dir ? Wb_hh : Wf_hh;
    const float* __restrict__ Wih  = dir ? Wb_ih : Wf_ih;
    const float* __restrict__ bias = dir ? bb    : bf;

    // one-time init (all 384 threads)
    for (int i = tid; i < 128 * 128; i += 384) {
        int r = i >> 7;
        int j = i & 127;
        int g = r >> 5, kl = r & 31;
        ull v = *(const ull*)(Whh + (size_t)(g * 256 + k0s + kl) * HDIM + 2 * j);
        Wp[(g * 128 + j) * 33 + kl] = v;
    }
    for (int i = tid; i < 2048; i += 384) hsm[i] = 0.f;   // h(-1)=0
    if (tid == 0) *xprog = 0;
    __syncthreads();

    if (tid >= 256) {
        // ================= LSTM half (warps 8-11, HIGH priority) =========
        const int ltid = tid - 256;        // 0..127
        const int lane = ltid & 31;
        const int warp = ltid >> 5;        // 0..3
        const int bA   = warp * 2;

        int* myflag = &g_flagsB[(((grp * 8) + ks) * 4 + warp) * 32];
        int* prodflags = lane < 8
            ? &g_flagsB[(((grp * 8) + (warp * 2 + (lane >> 2))) * 4 + (lane & 3)) * 32]
            : &g_flagsB[(((grp * 8) + warp * 2) * 4) * 32];

        const int base = *(volatile int*)myflag;

        const size_t ctaX = ((size_t)((dir * 8 + bt) * 8 + ks)) * (TT * 1024);
        const float* xmeA = g_X + ctaX + bA * 128 + lane;
        const float* xmeB = g_X + ctaX + (bA + 1) * 128 + lane;
        const size_t grpH = ((size_t)(dir * 8 + bt)) * (TT * 8 * HDIM);
        float* hmeA = g_h + grpH + bA * HDIM + (k0s + lane);
        float* hmeB = g_h + grpH + (bA + 1) * HDIM + (k0s + lane);
        const float* hsrc = g_h + grpH + (lane >> 2) * HDIM + warp * 64 + (lane & 3) * 16;
        float* hdst = hsm + warp * 512 + (lane >> 2) * 64 + (lane & 3) * 16;

        float cA = 0.f, cB = 0.f;

        for (int t = 0; t < TT; t++) {
            if (t > 0) {
                const int target = base + t;
                int fv = 0;
                bool done;
                do {
                    if (lane < 8)
                        asm volatile("ld.acquire.gpu.global.b32 %0, [%1];"
                                     : "=r"(fv) : "l"(prodflags) : "memory");
                    done = __all_sync(0xffffffffu, (lane >= 8) || (fv >= target));
                } while (!done);
                __syncwarp();

                const float* src = hsrc + (size_t)(t - 1) * (8 * HDIM);
                float4 v0 = *(const float4*)src;
                float4 v1 = *(const float4*)(src + 4);
                float4 v2 = *(const float4*)(src + 8);
                float4 v3 = *(const float4*)(src + 12);
                *(float4*)hdst        = v0;
                *(float4*)(hdst + 4)  = v1;
                *(float4*)(hdst + 8)  = v2;
                *(float4*)(hdst + 12) = v3;
                __syncwarp();
            }

            int xv;
            do {
                asm volatile("ld.acquire.cta.b32 %0, [%1];" : "=r"(xv) : "l"(xprog) : "memory");
            } while (xv < t + 1);

            const float* xrA = xmeA + (size_t)t * 1024;
            const float* xrB = xmeB + (size_t)t * 1024;
            float xiA = xrA[0], xfA = xrA[32], xgA = xrA[64], xoA = xrA[96];
            float xiB = xrB[0], xfB = xrB[32], xgB = xrB[64], xoB = xrB[96];

            // ---- partials over 64-wide kk window, h loaded in PAIRS ----
            ull acc[4][8];
#pragma unroll
            for (int g = 0; g < 4; g++)
#pragma unroll
                for (int b = 0; b < 8; b++) acc[g][b] = 0ull;

            const ull* hW = hsmu + warp * 256;   // [8b][32 kk-pairs]
            const int kkb = warp * 32;
#pragma unroll 2
            for (int c2 = 0; c2 < 16; c2++) {
                int kk2 = kkb + 2 * c2;
                ull w0a = Wp[(0 * 128 + kk2) * 33 + lane];
                ull w0b = Wp[(0 * 128 + kk2 + 1) * 33 + lane];
                ull w1a = Wp[(1 * 128 + kk2) * 33 + lane];
                ull w1b = Wp[(1 * 128 + kk2 + 1) * 33 + lane];
                ull w2a = Wp[(2 * 128 + kk2) * 33 + lane];
                ull w2b = Wp[(2 * 128 + kk2 + 1) * 33 + lane];
                ull w3a = Wp[(3 * 128 + kk2) * 33 + lane];
                ull w3b = Wp[(3 * 128 + kk2 + 1) * 33 + lane];
#pragma unroll
                for (int b = 0; b < 8; b++) {
                    ulonglong2 h01 = *(const ulonglong2*)&hW[b * 32 + 2 * c2];
                    acc[0][b] = ffma2(h01.x, w0a, acc[0][b]);
                    acc[0][b] = ffma2(h01.y, w0b, acc[0][b]);
                    acc[1][b] = ffma2(h01.x, w1a, acc[1][b]);
                    acc[1][b] = ffma2(h01.y, w1b, acc[1][b]);
                    acc[2][b] = ffma2(h01.x, w2a, acc[2][b]);
                    acc[2][b] = ffma2(h01.y, w2b, acc[2][b]);
                    acc[3][b] = ffma2(h01.x, w3a, acc[3][b]);
                    acc[3][b] = ffma2(h01.y, w3b, acc[3][b]);
                }
            }

            float* pb = ps + (t & 1) * 4096;
#pragma unroll
            for (int g = 0; g < 4; g++)
#pragma unroll
                for (int b = 0; b < 8; b++) {
                    float2 s = u2f2(acc[g][b]);
                    pb[((warp * 4 + g) * 8 + b) * 32 + lane] = s.x + s.y;
                }
            BARL();

            float sA0 = 0.f, sA1 = 0.f, sA2 = 0.f, sA3 = 0.f;
            float sB0 = 0.f, sB1 = 0.f, sB2 = 0.f, sB3 = 0.f;
#pragma unroll
            for (int w = 0; w < 4; w++) {
                sA0 += pb[((w * 4 + 0) * 8 + bA) * 32 + lane];
                sA1 += pb[((w * 4 + 1) * 8 + bA) * 32 + lane];
                sA2 += pb[((w * 4 + 2) * 8 + bA) * 32 + lane];
                sA3 += pb[((w * 4 + 3) * 8 + bA) * 32 + lane];
                sB0 += pb[((w * 4 + 0) * 8 + bA + 1) * 32 + lane];
                sB1 += pb[((w * 4 + 1) * 8 + bA + 1) * 32 + lane];
                sB2 += pb[((w * 4 + 2) * 8 + bA + 1) * 32 + lane];
                sB3 += pb[((w * 4 + 3) * 8 + bA + 1) * 32 + lane];
            }
            float giA = xiA + sA0, gfA = xfA + sA1, ggA = xgA + sA2, goA = xoA + sA3;
            float giB = xiB + sB0, gfB = xfB + sB1, ggB = xgB + sB2, goB = xoB + sB3;

            cA = sigf(gfA) * cA + sigf(giA) * tanhf(ggA);
            float hA = sigf(goA) * tanhf(cA);
            cB = sigf(gfB) * cB + sigf(giB) * tanhf(ggB);
            float hB = sigf(goB) * tanhf(cB);
            hmeA[(size_t)t * (8 * HDIM)] = hA;
            hmeB[(size_t)t * (8 * HDIM)] = hB;

            if (t + 1 < TT) {
                __syncwarp();
                if (lane == 0)
                    asm volatile("st.release.gpu.global.b32 [%0], %1;"
                                 :: "l"(myflag), "r"(base + t + 1) : "memory");
            }
        }
    } else {
        // ===== GEMM half (warps 0-7): tile M=128 (16 t x 8 b) x N=128 ====
        const int tid2 = tid;              // 0..255
        const int tx = tid2 & 15;          // n oct: cols tx*8..+7
        const int ty = tid2 >> 4;          // m oct: rows ty*8..+7
        const int lrow = tid2 >> 1;        // load row 0..127
        const int kc8  = (tid2 & 1) * 8;   // k chunk
        const size_t xbase = ((size_t)((dir * 8 + bt) * 8 + ks)) * (TT * 1024);

        // bias for my 8 n-cols (constant across mt)
        const int ng = tx * 8;
        const float* bp2 = bias + (ng >> 5) * 256 + k0s + (ng & 31);
        float4 bv40 = *(const float4*)bp2;
        float4 bv41 = *(const float4*)(bp2 + 4);

        for (int mt = 0; mt < 32; mt++) {
            if (tid2 < 128) {
                int tloc = tid2 >> 3, b_l = tid2 & 7;
                int t = mt * 16 + tloc, b = b0 + b_l;
                int tt = t;
                if (dir) { int len = lengths[b]; tt = (t < len) ? (len - 1 - t) : t; }
                tok2[tid2] = sentence[b * TT + tt];
            }
            BARG();

            const float* erow = emb + (size_t)tok2[lrow] * EE;
            const float* wrow = Wih + (size_t)((lrow >> 5) * 256 + k0s + (lrow & 31)) * EE;

            ull acc[4][8];
#pragma unroll
            for (int i = 0; i < 4; i++)
#pragma unroll
                for (int j = 0; j < 8; j++) acc[i][j] = 0ull;

            for (int k0 = 0; k0 < 304; k0 += 16) {
                const int kb = k0 + kc8;
                // A tile [k][m] (8 floats/thread, transposed store)
                if (kb + 8 <= EE) {
                    float4 v0 = *(const float4*)(erow + kb);
                    float4 v1 = *(const float4*)(erow + kb + 4);
                    As[(kc8 + 0) * 132 + lrow] = v0.x;
                    As[(kc8 + 1) * 132 + lrow] = v0.y;
                    As[(kc8 + 2) * 132 + lrow] = v0.z;
                    As[(kc8 + 3) * 132 + lrow] = v0.w;
                    As[(kc8 + 4) * 132 + lrow] = v1.x;
                    As[(kc8 + 5) * 132 + lrow] = v1.y;
                    As[(kc8 + 6) * 132 + lrow] = v1.z;
                    As[(kc8 + 7) * 132 + lrow] = v1.w;
                } else {
#pragma unroll
                    for (int i = 0; i < 8; i++)
                        As[(kc8 + i) * 132 + lrow] = (kb + i < EE) ? erow[kb + i] : 0.f;
                }
                // B tile [k][n]
                if (kb + 8 <= EE) {
                    float4 v0 = *(const float4*)(wrow + kb);
                    float4 v1 = *(const float4*)(wrow + kb + 4);
                    Bs[(kc8 + 0) * 132 + lrow] = v0.x;
                    Bs[(kc8 + 1) * 132 + lrow] = v0.y;
                    Bs[(kc8 + 2) * 132 + lrow] = v0.z;
                    Bs[(kc8 + 3) * 132 + lrow] = v0.w;
                    Bs[(kc8 + 4) * 132 + lrow] = v1.x;
                    Bs[(kc8 + 5) * 132 + lrow] = v1.y;
                    Bs[(kc8 + 6) * 132 + lrow] = v1.z;
                    Bs[(kc8 + 7) * 132 + lrow] = v1.w;
                } else {
#pragma unroll
                    for (int i = 0; i < 8; i++)
                        Bs[(kc8 + i) * 132 + lrow] = (kb + i < EE) ? wrow[kb + i] : 0.f;
                }
                BARG();

#pragma unroll
                for (int kk = 0; kk < 16; kk++) {
                    ulonglong2 a0 = *(const ulonglong2*)&As[kk * 132 + ty * 8];
                    ulonglong2 a1 = *(const ulonglong2*)&As[kk * 132 + ty * 8 + 4];
                    float4 b0 = *(const float4*)&Bs[kk * 132 + tx * 8];
                    float4 b1 = *(const float4*)&Bs[kk * 132 + tx * 8 + 4];
                    ull q0 = f2u2(b0.x, b0.x);
                    ull q1 = f2u2(b0.y, b0.y);
                    ull q2 = f2u2(b0.z, b0.z);
                    ull q3 = f2u2(b0.w, b0.w);
                    ull q4 = f2u2(b1.x, b1.x);
                    ull q5 = f2u2(b1.y, b1.y);
                    ull q6 = f2u2(b1.z, b1.z);
                    ull q7 = f2u2(b1.w, b1.w);
                    acc[0][0] = ffma2(a0.x, q0, acc[0][0]);
                    acc[0][1] = ffma2(a0.x, q1, acc[0][1]);
                    acc[0][2] = ffma2(a0.x, q2, acc[0][2]);
                    acc[0][3] = ffma2(a0.x, q3, acc[0][3]);
                    acc[0][4] = ffma2(a0.x, q4, acc[0][4]);
                    acc[0][5] = ffma2(a0.x, q5, acc[0][5]);
                    acc[0][6] = ffma2(a0.x, q6, acc[0][6]);
                    acc[0][7] = ffma2(a0.x, q7, acc[0][7]);
                    acc[1][0] = ffma2(a0.y, q0, acc[1][0]);
                    acc[1][1] = ffma2(a0.y, q1, acc[1][1]);
                    acc[1][2] = ffma2(a0.y, q2, acc[1][2]);
                    acc[1][3] = ffma2(a0.y, q3, acc[1][3]);
                    acc[1][4] = ffma2(a0.y, q4, acc[1][4]);
                    acc[1][5] = ffma2(a0.y, q5, acc[1][5]);
                    acc[1][6] = ffma2(a0.y, q6, acc[1][6]);
                    acc[1][7] = ffma2(a0.y, q7, acc[1][7]);
                    acc[2][0] = ffma2(a1.x, q0, acc[2][0]);
                    acc[2][1] = ffma2(a1.x, q1, acc[2][1]);
                    acc[2][2] = ffma2(a1.x, q2, acc[2][2]);
                    acc[2][3] = ffma2(a1.x, q3, acc[2][3]);
                    acc[2][4] = ffma2(a1.x, q4, acc[2][4]);
                    acc[2][5] = ffma2(a1.x, q5, acc[2][5]);
                    acc[2][6] = ffma2(a1.x, q6, acc[2][6]);
                    acc[2][7] = ffma2(a1.x, q7, acc[2][7]);
                    acc[3][0] = ffma2(a1.y, q0, acc[3][0]);
                    acc[3][1] = ffma2(a1.y, q1, acc[3][1]);
                    acc[3][2] = ffma2(a1.y, q2, acc[3][2]);
                    acc[3][3] = ffma2(a1.y, q3, acc[3][3]);
                    acc[3][4] = ffma2(a1.y, q4, acc[3][4]);
                    acc[3][5] = ffma2(a1.y, q5, acc[3][5]);
                    acc[3][6] = ffma2(a1.y, q6, acc[3][6]);
                    acc[3][7] = ffma2(a1.y, q7, acc[3][7]);
                }
                BARG();
            }

            // epilogue: 8m x 8n per thread
#pragma unroll
            for (int mp = 0; mp < 4; mp++) {
                float2 c0 = u2f2(acc[mp][0]);
                float2 c1 = u2f2(acc[mp][1]);
                float2 c2 = u2f2(acc[mp][2]);
                float2 c3 = u2f2(acc[mp][3]);
                float2 c4 = u2f2(acc[mp][4]);
                float2 c5 = u2f2(acc[mp][5]);
                float2 c6 = u2f2(acc[mp][6]);
                float2 c7 = u2f2(acc[mp][7]);
#pragma unroll
                for (int h = 0; h < 2; h++) {
                    int m = ty * 8 + 2 * mp + h;
                    int tloc = m >> 3, b_l = m & 7;
                    size_t off = xbase + (size_t)(mt * 16 + tloc) * 1024 + b_l * 128 + ng;
                    float4 vA, vB;
                    if (h == 0) {
                        vA.x = c0.x + bv40.x; vA.y = c1.x + bv40.y; vA.z = c2.x + bv40.z; vA.w = c3.x + bv40.w;
                        vB.x = c4.x + bv41.x; vB.y = c5.x + bv41.y; vB.z = c6.x + bv41.z; vB.w = c7.x + bv41.w;
                    } else {
                        vA.x = c0.y + bv40.x; vA.y = c1.y + bv40.y; vA.z = c2.y + bv40.z; vA.w = c3.y + bv40.w;
                        vB.x = c4.y + bv41.x; vB.y = c5.y + bv41.y; vB.z = c6.y + bv41.z; vB.w = c7.y + bv41.w;
                    }
                    *(float4*)&g_X[off]     = vA;
                    *(float4*)&g_X[off + 4] = vB;
                }
            }
            BARG();
            if (tid2 == 0) {
                int val = (mt + 1) * 16;
                asm volatile("st.release.cta.b32 [%0], %1;" :: "l"(xprog), "r"(val) : "memory");
            }
        }
    }
}

// =====================================================================
// Kernel 3: emissions (unchanged)
// =====================================================================
__global__ void emis_kernel(const int* __restrict__ lengths,
                            const float* __restrict__ W_out,
                            const float* __restrict__ b_out)
{
    __shared__ float Wsm[KTAG * 2 * HDIM];
    __shared__ float bsm[KTAG];

    const int tid = threadIdx.x;
    for (int i = tid; i < KTAG * 2 * HDIM; i += 256) Wsm[i] = W_out[i];
    if (tid < KTAG) bsm[tid] = b_out[tid];
    __syncthreads();

    const int warp = tid >> 5;
    const int lane = tid & 31;
    const int r = blockIdx.x * 8 + warp;
    const int b = r >> 9;
    const int t = r & 511;
    const int len = lengths[b];
    const int tr  = (t < len) ? (len - 1 - t) : t;
    const int bt = b >> 3, b_l = b & 7;

    const float* hf = g_h + ((size_t)(0 * 8 + bt)) * (TT * 8 * HDIM)
                          + (size_t)t  * (8 * HDIM) + b_l * HDIM;
    const float* hb = g_h + ((size_t)(1 * 8 + bt)) * (TT * 8 * HDIM)
                          + (size_t)tr * (8 * HDIM) + b_l * HDIM;

    float x[16];
#pragma unroll
    for (int i = 0; i < 8; i++) x[i]     = hf[lane + 32 * i];
#pragma unroll
    for (int i = 0; i < 8; i++) x[8 + i] = hb[lane + 32 * i];

    for (int kk = 0; kk < KTAG; kk++) {
        const float* w = Wsm + (size_t)kk * (2 * HDIM);
        float s = 0.f;
#pragma unroll
        for (int i = 0; i < 8; i++) s += x[i]     * w[lane + 32 * i];
#pragma unroll
        for (int i = 0; i < 8; i++) s += x[8 + i] * w[HDIM + lane + 32 * i];
#pragma unroll
        for (int off = 16; off; off >>= 1) s += __shfl_xor_sync(0xffffffffu, s, off);
        if (lane == 0) g_emis[((size_t)b * TT + t) * KTAG + kk] = s + bsm[kk];
    }
}

// =====================================================================
// Kernel 4: Viterbi (unchanged)
// =====================================================================
#define VIT_SMEM 53248
#define VCOMB(av, ai_, bv, bi_) { if ((bv) > (av)) { (av) = (bv); (ai_) = (bi_); } }

__global__ void viterbi_kernel(const int* __restrict__ lengths,
                               const int* __restrict__ stop_id_p,
                               const float* __restrict__ trans,
                               float* __restrict__ out)
{
    extern __shared__ char vsm[];
    float* emis_s = (float*)vsm;
    float* trp    = emis_s + TT * KTAG;
    float* term   = trp + KTAG * 21;
    unsigned char* bp = (unsigned char*)(term + KTAG);

    const int b = blockIdx.x;
    const int lane = threadIdx.x;

    for (int i = lane; i < TT * KTAG; i += 32)
        emis_s[i] = g_emis[(size_t)b * TT * KTAG + i];
    for (int i = lane; i < KTAG * KTAG; i += 32)
        trp[(i / KTAG) * 21 + (i % KTAG)] = trans[i];
    __syncwarp();

    const int len  = lengths[b];
    const int stop = *stop_id_p;
    const float* trl = trp + (lane < KTAG ? lane : 0) * 21;

    float d = 0.f;

    for (int t = 0; t < TT; t++) {
        float em = (lane < KTAG) ? emis_s[t * KTAG + lane] : 0.f;

        float v[KTAG];
#pragma unroll
        for (int p = 0; p < KTAG; p++)
            v[p] = __shfl_sync(0xffffffffu, d, p) + trl[p];

        float w10[10]; int i10[10];
#pragma unroll
        for (int i = 0; i < 10; i++) {
            w10[i] = v[2 * i]; i10[i] = 2 * i;
            VCOMB(w10[i], i10[i], v[2 * i + 1], 2 * i + 1);
        }
        float w5[5]; int i5[5];
#pragma unroll
        for (int i = 0; i < 5; i++) {
            w5[i] = w10[2 * i]; i5[i] = i10[2 * i];
            VCOMB(w5[i], i5[i], w10[2 * i + 1], i10[2 * i + 1]);
        }
        float bv0 = w5[0]; int bi0 = i5[0];
        VCOMB(bv0, bi0, w5[1], i5[1]);
        float bv1 = w5[2]; int bi1 = i5[2];
        VCOMB(bv1, bi1, w5[3], i5[3]);
        VCOMB(bv0, bi0, bv1, bi1);
        VCOMB(bv0, bi0, w5[4], i5[4]);

        bool valid = (t < len);
        if (lane < KTAG) {
            float nd = bv0 + em;
            int bpv  = valid ? bi0 : lane;
            d = valid ? nd : d;
            bp[t * KTAG + lane] = (unsigned char)bpv;
        }
    }

    if (lane < KTAG) term[lane] = d + trp[stop * 21 + lane];
    __syncwarp();

    if (lane == 0) {
        float best = -3.4e38f; int arg = 0;
        for (int j = 0; j < KTAG; j++)
            if (term[j] > best) { best = term[j]; arg = j; }
        out[b] = best;
        float* po = out + BB + (size_t)b * (TT + 1);
        po[TT] = (float)arg;
        int tag = arg;
        for (int t = TT - 1; t >= 0; t--) {
            tag = bp[t * KTAG + tag];
            po[t] = (float)tag;
        }
    }
}

// =====================================================================
// launch
// =====================================================================
extern "C" void kernel_launch(void* const* d_in, const int* in_sizes, int n_in,
                              void* d_out, int out_size)
{
    (void)in_sizes; (void)n_in; (void)out_size;
    const int*   sentence = (const int*)d_in[0];
    const int*   lengths  = (const int*)d_in[1];
    const int*   stop_id  = (const int*)d_in[3];
    const float* emb      = (const float*)d_in[4];
    const float* Wf_ih    = (const float*)d_in[5];
    const float* Wf_hh    = (const float*)d_in[6];
    const float* bf       = (const float*)d_in[7];
    const float* Wb_ih    = (const float*)d_in[8];
    const float* Wb_hh    = (const float*)d_in[9];
    const float* bb       = (const float*)d_in[10];
    const float* W_out    = (const float*)d_in[11];
    const float* b_out    = (const float*)d_in[12];
    const float* trans    = (const float*)d_in[13];
    float* out = (float*)d_out;

    static int attr_set = 0;
    if (!attr_set) {
        cudaFuncSetAttribute(fused_persistent_kernel,
                             cudaFuncAttributeMaxDynamicSharedMemorySize, SMEM_FUSED);
        cudaFuncSetAttribute(viterbi_kernel,
                             cudaFuncAttributeMaxDynamicSharedMemorySize, VIT_SMEM);
        attr_set = 1;
    }

    fused_persistent_kernel<<<GRID_P, 384, SMEM_FUSED>>>(
        sentence, lengths, emb, Wf_ih, bf, Wb_ih, bb, Wf_hh, Wb_hh);

    emis_kernel<<<BB * TT / 8, 256>>>(lengths, W_out, b_out);

    viterbi_kernel<<<BB, 32, VIT_SMEM>>>(lengths, stop_id, trans, out);
}